// round 10
// baseline (speedup 1.0000x reference)
#include <cuda_runtime.h>
#include <cuda_bf16.h>
#include <cstdint>

#define F 26
#define D 128
#define NROWS 100000
#define B 4096
#define T (B * 20)
#define THRESH 48   // bags longer than this go to the cooperative kernel

// ---- shared per-warp gather pipeline -------------------------------------
// Lane l owns the l-th float4 (16B) of each 512B row. Rows go global->shared
// via cp.async, stages of 4 rows, double buffered (8 slots = 4KB per warp).
// Accumulates rows [lo, hi) of vals into a float4 (per-lane slice of the sum).
__device__ __forceinline__ float4 gather_accum(
    const int* __restrict__ vals, int lo, int hi,
    const char* __restrict__ tabb, uint32_t sb0 /*smem byte addr of slot0 for this lane*/,
    int lane, float4* __restrict__ bufw /*&buf[warp][0][0]*/)
{
    float4 a0 = make_float4(0.f, 0.f, 0.f, 0.f);
    float4 a1 = make_float4(0.f, 0.f, 0.f, 0.f);

    for (int base = lo; base < hi; base += 32) {
        const int n = min(32, hi - base);
        int myidx = 0;
        if (base + lane < hi) myidx = __ldg(vals + base + lane);

        const int nstage = (n + 3) >> 2;
        int sbuf = 0;
        int prevcnt = 0;

        for (int st = 0; st < nstage; ++st) {
            const int cnt = min(4, n - st * 4);
            #pragma unroll
            for (int q = 0; q < 4; ++q) {
                if (q < cnt) {
                    int r = __shfl_sync(0xffffffffu, myidx, st * 4 + q);
                    const char* src = tabb + ((size_t)(unsigned)r << 9) + (lane << 4);
                    uint32_t dst = sb0 + (uint32_t)((sbuf * 4 + q) << 9);
                    asm volatile("cp.async.cg.shared.global [%0], [%1], 16;\n"
                                 :: "r"(dst), "l"(src));
                }
            }
            asm volatile("cp.async.commit_group;\n");

            if (st > 0) {
                asm volatile("cp.async.wait_group 1;\n");
                const int pb = (sbuf ^ 1) * 4;
                #pragma unroll
                for (int q = 0; q < 4; ++q) {
                    if (q < prevcnt) {
                        float4 v = bufw[(pb + q) * 32 + lane];
                        if (q & 1) { a1.x += v.x; a1.y += v.y; a1.z += v.z; a1.w += v.w; }
                        else       { a0.x += v.x; a0.y += v.y; a0.z += v.z; a0.w += v.w; }
                    }
                }
            }
            prevcnt = cnt;
            sbuf ^= 1;
        }

        if (nstage > 0) {
            asm volatile("cp.async.wait_group 0;\n");
            const int pb = (sbuf ^ 1) * 4;
            #pragma unroll
            for (int q = 0; q < 4; ++q) {
                if (q < prevcnt) {
                    float4 v = bufw[(pb + q) * 32 + lane];
                    if (q & 1) { a1.x += v.x; a1.y += v.y; a1.z += v.z; a1.w += v.w; }
                    else       { a0.x += v.x; a0.y += v.y; a0.z += v.z; a0.w += v.w; }
                }
            }
        }
    }

    float4 acc;
    acc.x = a0.x + a1.x; acc.y = a0.y + a1.y;
    acc.z = a0.z + a1.z; acc.w = a0.w + a1.w;
    return acc;
}

// ---- Kernel S: short bags (len <= THRESH), warp per bag -------------------
__global__ __launch_bounds__(64, 24) void ebag_short(
    const float* __restrict__ tables,
    const int* __restrict__ values,
    const int* __restrict__ offsets,
    float* __restrict__ out)
{
    __shared__ float4 buf[2][8][32];   // 8KB

    const int lane = threadIdx.x & 31;
    const int warp = threadIdx.x >> 5;
    const int bag  = blockIdx.x * 2 + warp;
    const int f    = blockIdx.y;

    const int* offs = offsets + f * (B + 1);
    const int s = __ldg(offs + bag);
    const int e = __ldg(offs + bag + 1);
    if (e - s > THRESH) return;        // handled by ebag_long

    const int* vals = values + (size_t)f * T;
    const char* tabb = reinterpret_cast<const char*>(tables + (size_t)f * NROWS * D);
    uint32_t sb0 = (uint32_t)__cvta_generic_to_shared(&buf[warp][0][lane]);

    float4 acc = gather_accum(vals, s, e, tabb, sb0, lane, &buf[warp][0][0]);

    float4* o = reinterpret_cast<float4*>(out) + ((size_t)bag * F + f) * 32;
    o[lane] = acc;
}

// ---- Kernel L: long bags (len > THRESH), 8 warps cooperate ----------------
// Each block scans a strip of 16 bags; long ones are split contiguously over
// the 8 warps, partials combined through smem by warp 0.
__global__ __launch_bounds__(256) void ebag_long(
    const float* __restrict__ tables,
    const int* __restrict__ values,
    const int* __restrict__ offsets,
    float* __restrict__ out)
{
    __shared__ float4 buf[8][8][32];   // 32KB: per-warp pipeline rings
    __shared__ float4 red[8][32];      // 4KB:  per-warp partial sums

    const int lane = threadIdx.x & 31;
    const int warp = threadIdx.x >> 5;
    const int f    = blockIdx.y;
    const int bag0 = blockIdx.x * 16;

    const int* offs = offsets + f * (B + 1);
    const int* vals = values + (size_t)f * T;
    const char* tabb = reinterpret_cast<const char*>(tables + (size_t)f * NROWS * D);
    uint32_t sb0 = (uint32_t)__cvta_generic_to_shared(&buf[warp][0][lane]);

    for (int bi = 0; bi < 16; ++bi) {
        const int bag = bag0 + bi;
        const int s = __ldg(offs + bag);
        const int e = __ldg(offs + bag + 1);
        const int len = e - s;
        if (len <= THRESH) continue;   // handled by ebag_short

        // contiguous 8-way split
        const int L  = (len + 7) >> 3;
        const int lo = s + warp * L;
        const int hi = min(lo + L, e);

        float4 acc = make_float4(0.f, 0.f, 0.f, 0.f);
        if (lo < hi)
            acc = gather_accum(vals, lo, hi, tabb, sb0, lane, &buf[warp][0][0]);

        red[warp][lane] = acc;
        __syncthreads();

        if (warp == 0) {
            float4 t = red[0][lane];
            #pragma unroll
            for (int w = 1; w < 8; ++w) {
                float4 v = red[w][lane];
                t.x += v.x; t.y += v.y; t.z += v.z; t.w += v.w;
            }
            float4* o = reinterpret_cast<float4*>(out) + ((size_t)bag * F + f) * 32;
            o[lane] = t;
        }
        __syncthreads();               // red[] reuse safety
    }
}

extern "C" void kernel_launch(void* const* d_in, const int* in_sizes, int n_in,
                              void* d_out, int out_size) {
    const float* tables  = (const float*)d_in[0];
    const int*   values  = (const int*)d_in[1];
    const int*   offsets = (const int*)d_in[2];
    float* out = (float*)d_out;

    // Long bags first (they are the stragglers), then the short-bag sweep.
    dim3 gridL(B / 16, F);
    ebag_long<<<gridL, 256>>>(tables, values, offsets, out);

    dim3 gridS(B / 2, F);
    ebag_short<<<gridS, 64>>>(tables, values, offsets, out);
}

// round 11
// speedup vs baseline: 1.1752x; 1.1752x over previous
#include <cuda_runtime.h>
#include <cuda_bf16.h>
#include <cstdint>

#define F 26
#define D 128
#define NROWS 100000
#define B 4096
#define T (B * 20)

// ---- per-warp gather pipeline ---------------------------------------------
// Lane l owns the l-th float4 (16B) of each 512B row. Rows go global->shared
// via cp.async, stages of 4 rows, double buffered (8 slots = 4KB per warp).
// Accumulates rows [lo, hi) of vals into a per-lane float4 slice of the sum.
__device__ __forceinline__ float4 gather_accum(
    const int* __restrict__ vals, int lo, int hi,
    const char* __restrict__ tabb, uint32_t sb0,
    int lane, const float4* __restrict__ bufw)
{
    float4 a0 = make_float4(0.f, 0.f, 0.f, 0.f);
    float4 a1 = make_float4(0.f, 0.f, 0.f, 0.f);

    for (int base = lo; base < hi; base += 32) {
        const int n = min(32, hi - base);
        int myidx = 0;
        if (base + lane < hi) myidx = __ldg(vals + base + lane);

        const int nstage = (n + 3) >> 2;
        int sbuf = 0;
        int prevcnt = 0;

        for (int st = 0; st < nstage; ++st) {
            const int cnt = min(4, n - st * 4);
            #pragma unroll
            for (int q = 0; q < 4; ++q) {
                if (q < cnt) {
                    int r = __shfl_sync(0xffffffffu, myidx, st * 4 + q);
                    const char* src = tabb + ((size_t)(unsigned)r << 9) + (lane << 4);
                    uint32_t dst = sb0 + (uint32_t)((sbuf * 4 + q) << 9);
                    asm volatile("cp.async.cg.shared.global [%0], [%1], 16;\n"
                                 :: "r"(dst), "l"(src));
                }
            }
            asm volatile("cp.async.commit_group;\n");

            if (st > 0) {
                asm volatile("cp.async.wait_group 1;\n");
                const int pb = (sbuf ^ 1) * 4;
                #pragma unroll
                for (int q = 0; q < 4; ++q) {
                    if (q < prevcnt) {
                        float4 v = bufw[(pb + q) * 32 + lane];
                        if (q & 1) { a1.x += v.x; a1.y += v.y; a1.z += v.z; a1.w += v.w; }
                        else       { a0.x += v.x; a0.y += v.y; a0.z += v.z; a0.w += v.w; }
                    }
                }
            }
            prevcnt = cnt;
            sbuf ^= 1;
        }

        if (nstage > 0) {
            asm volatile("cp.async.wait_group 0;\n");
            const int pb = (sbuf ^ 1) * 4;
            #pragma unroll
            for (int q = 0; q < 4; ++q) {
                if (q < prevcnt) {
                    float4 v = bufw[(pb + q) * 32 + lane];
                    if (q & 1) { a1.x += v.x; a1.y += v.y; a1.z += v.z; a1.w += v.w; }
                    else       { a0.x += v.x; a0.y += v.y; a0.z += v.z; a0.w += v.w; }
                }
            }
        }
    }

    float4 acc;
    acc.x = a0.x + a1.x; acc.y = a0.y + a1.y;
    acc.z = a0.z + a1.z; acc.w = a0.w + a1.w;
    return acc;
}

// ---- fused, sum-split kernel ----------------------------------------------
// Block = 8 warps = 8 consecutive bags of one feature. Offsets are cumulative,
// so the 8 bags occupy ONE contiguous range of vals. That range is split
// EVENLY over the 8 warps (each warp ~ total/8 rows, crossing bag boundaries
// as needed) -> zero intra-block imbalance; long bags auto-spread over warps.
// Per-bag partials combine via smem atomicAdd; warp w writes bag w.
__global__ __launch_bounds__(256, 6) void ebag_fused(
    const float* __restrict__ tables,   // [F, NROWS, D]
    const int* __restrict__ values,     // [F, T]
    const int* __restrict__ offsets,    // [F, B+1]
    float* __restrict__ out)            // [B, F, D]
{
    __shared__ float4 buf[8][8][32];            // 32KB: per-warp pipeline rings
    __shared__ __align__(16) float part[8][128]; // 4KB: per-bag partial sums

    const int lane = threadIdx.x & 31;
    const int warp = threadIdx.x >> 5;
    const int f    = blockIdx.y;
    const int bag0 = blockIdx.x * 8;

    const int* offs = offsets + f * (B + 1);
    // 9 boundary offsets held warp-wide in one register, fetched via shfl.
    int off_l = 0;
    if (lane < 9) off_l = __ldg(offs + bag0 + lane);

    // zero the partial buffer (256 threads x 4 floats = 1024 floats)
    reinterpret_cast<float4*>(&part[0][0])[threadIdx.x] =
        make_float4(0.f, 0.f, 0.f, 0.f);
    __syncthreads();

    const int S = __shfl_sync(0xffffffffu, off_l, 0);
    const int E = __shfl_sync(0xffffffffu, off_l, 8);
    const int total = E - S;

    const int* vals = values + (size_t)f * T;
    const char* tabb = reinterpret_cast<const char*>(
        tables + (size_t)f * NROWS * D);
    uint32_t sb0 = (uint32_t)__cvta_generic_to_shared(&buf[warp][0][lane]);

    // this warp's even share of the concatenated range
    int lo = S + (int)(((long long)total * warp) >> 3);
    int hi = S + (int)(((long long)total * (warp + 1)) >> 3);

    if (lo < hi) {
        // find first bag j containing lo: largest j with offs[j] <= lo
        int j = 0;
        int oj1 = __shfl_sync(0xffffffffu, off_l, 1);
        while (j < 7) {
            if (oj1 > lo) break;
            ++j;
            oj1 = __shfl_sync(0xffffffffu, off_l, j + 1);
        }

        int p = lo;
        while (p < hi) {
            const int ce = min(hi, oj1);        // chunk end within bag j
            if (ce > p) {
                float4 acc = gather_accum(vals, p, ce, tabb, sb0, lane,
                                          &buf[warp][0][0]);
                float* pj = &part[j][lane * 4];
                atomicAdd(pj + 0, acc.x);
                atomicAdd(pj + 1, acc.y);
                atomicAdd(pj + 2, acc.z);
                atomicAdd(pj + 3, acc.w);
                p = ce;
            }
            if (p >= hi) break;
            ++j;
            oj1 = __shfl_sync(0xffffffffu, off_l, j + 1);
        }
    }
    __syncthreads();

    // warp w writes bag w (always: empty bags must be 0, d_out is poisoned)
    float4 res = reinterpret_cast<const float4*>(&part[warp][0])[lane];
    float4* o = reinterpret_cast<float4*>(out) + ((size_t)(bag0 + warp) * F + f) * 32;
    o[lane] = res;
}

extern "C" void kernel_launch(void* const* d_in, const int* in_sizes, int n_in,
                              void* d_out, int out_size) {
    const float* tables  = (const float*)d_in[0];
    const int*   values  = (const int*)d_in[1];
    const int*   offsets = (const int*)d_in[2];
    float* out = (float*)d_out;

    dim3 grid(B / 8, F);   // feature on y: blocks of one feature grouped -> L2 reuse
    dim3 block(256);       // 8 warps, 8 bags, sum-split evenly
    ebag_fused<<<grid, block>>>(tables, values, offsets, out);
}